// round 5
// baseline (speedup 1.0000x reference)
#include <cuda_runtime.h>

#define POOL 7
#define NUM_ROIS 300
#define IMG_H 200
#define IMG_W 200
#define IMG_C 512
#define NPOS (NUM_ROIS * POOL * POOL)   // 14700
#define NUM_SMS 148
#define CTAS_PER_SM 16

// Persistent grid-stride kernel: one wave of CTAs, each looping over output
// positions (roi, py, px). 128 threads, 4 channels each (float4), MLP=4 per
// iteration; independent iterations let the scheduler overlap next-iteration
// loads with current waits. __launch_bounds__(128,16) pins regs<=32 so the
// full 64 warps/SM are resident.
__global__ __launch_bounds__(128, 16) void roi_pool_kernel(
    const float* __restrict__ img,   // [H, W, C]
    const float* __restrict__ rois,  // [NUM_ROIS, 4] (x, y, w, h) as float
    float* __restrict__ out)         // [NUM_ROIS, POOL, POOL, C]
{
    const int c = threadIdx.x * 4;   // channel base

    for (int b = blockIdx.x; b < NPOS; b += gridDim.x) {
        const int roi = b / (POOL * POOL);
        const int pos = b - roi * (POOL * POOL);
        const int py  = pos / POOL;
        const int px  = pos - py * POOL;

        // ---- ROI geometry (uniform across block; rois stay L1-hot) ----
        const int rx = (int)__ldg(&rois[roi * 4 + 0]);
        const int ry = (int)__ldg(&rois[roi * 4 + 1]);
        const int rw = (int)__ldg(&rois[roi * 4 + 2]);
        const int rh = (int)__ldg(&rois[roi * 4 + 3]);

        const int x0 = min(max(rx, 0), IMG_W - 1);
        const int y0 = min(max(ry, 0), IMG_H - 1);
        const int w  = min(max(rw, 1), IMG_W - x0);
        const int h  = min(max(rh, 1), IMG_H - y0);

        // TF1 resize (align_corners=False): src = dst * (in/out); exact fp32 div
        const float sx = (float)w / (float)POOL;
        const float sy = (float)h / (float)POOL;
        const float xs = (float)px * sx;
        const float ys = (float)py * sy;

        int ix0 = (int)floorf(xs);
        int iy0 = (int)floorf(ys);
        const float fx = xs - (float)ix0;   // frac BEFORE clamp (matches ref)
        const float fy = ys - (float)iy0;
        ix0 = min(ix0, w - 1);
        iy0 = min(iy0, h - 1);
        const int ix1 = min(ix0 + 1, w - 1);
        const int iy1 = min(iy0 + 1, h - 1);

        const int r0 = (y0 + iy0) * IMG_W;
        const int r1 = (y0 + iy1) * IMG_W;

        const float4 v00 = *(const float4*)(img + (long)(r0 + x0 + ix0) * IMG_C + c);
        const float4 v01 = *(const float4*)(img + (long)(r0 + x0 + ix1) * IMG_C + c);
        const float4 v10 = *(const float4*)(img + (long)(r1 + x0 + ix0) * IMG_C + c);
        const float4 v11 = *(const float4*)(img + (long)(r1 + x0 + ix1) * IMG_C + c);

        const float gx = 1.0f - fx;
        const float gy = 1.0f - fy;

        float4 r;
        r.x = (v00.x * gx + v01.x * fx) * gy + (v10.x * gx + v11.x * fx) * fy;
        r.y = (v00.y * gx + v01.y * fx) * gy + (v10.y * gx + v11.y * fx) * fy;
        r.z = (v00.z * gx + v01.z * fx) * gy + (v10.z * gx + v11.z * fx) * fy;
        r.w = (v00.w * gx + v01.w * fx) * gy + (v10.w * gx + v11.w * fx) * fy;

        __stcs((float4*)(out + (long)b * IMG_C + c), r);
    }
}

extern "C" void kernel_launch(void* const* d_in, const int* in_sizes, int n_in,
                              void* d_out, int out_size)
{
    const float* img  = (const float*)d_in[0];
    const float* rois = (const float*)d_in[1];
    float* out = (float*)d_out;

    const int nblocks = NUM_SMS * CTAS_PER_SM;  // 2368 persistent CTAs, 1 wave
    roi_pool_kernel<<<nblocks, 128>>>(img, rois, out);
}

// round 6
// speedup vs baseline: 1.0021x; 1.0021x over previous
#include <cuda_runtime.h>

#define POOL 7
#define NUM_ROIS 300
#define IMG_H 200
#define IMG_W 200
#define IMG_C 512

__device__ __forceinline__ float4 bilerp(float4 v00, float4 v01,
                                         float4 v10, float4 v11,
                                         float fx, float fy)
{
    const float gx = 1.0f - fx;
    const float gy = 1.0f - fy;
    float4 r;
    r.x = (v00.x * gx + v01.x * fx) * gy + (v10.x * gx + v11.x * fx) * fy;
    r.y = (v00.y * gx + v01.y * fx) * gy + (v10.y * gx + v11.y * fx) * fy;
    r.z = (v00.z * gx + v01.z * fx) * gy + (v10.z * gx + v11.z * fx) * fy;
    r.w = (v00.w * gx + v01.w * fx) * gy + (v10.w * gx + v11.w * fx) * fy;
    return r;
}

// CTA = (roi, py-set) where py-sets are {0,1},{2,3},{4,5},{6}.
// 128 threads, 4 channels each (float4). Consecutive px share corner columns
// and consecutive py share corner rows -> the repeated 2KB pixel vectors hit
// L1 instead of L2, cutting LTS read traffic (the chip-level bottleneck).
__global__ __launch_bounds__(128) void roi_pool_kernel(
    const float* __restrict__ img,   // [H, W, C]
    const float* __restrict__ rois,  // [NUM_ROIS, 4] (x, y, w, h) as float
    float* __restrict__ out)         // [NUM_ROIS, POOL, POOL, C]
{
    const int b    = blockIdx.x;          // 0..1199
    const int roi  = b >> 2;
    const int set  = b & 3;
    const int pyA  = set * 2;             // first py of this set
    const int npy  = (set == 3) ? 1 : 2;  // set 3 covers only py=6
    const int c    = threadIdx.x * 4;     // channel base

    // ---- ROI geometry (uniform across block) ----
    const int rx = (int)__ldg(&rois[roi * 4 + 0]);
    const int ry = (int)__ldg(&rois[roi * 4 + 1]);
    const int rw = (int)__ldg(&rois[roi * 4 + 2]);
    const int rh = (int)__ldg(&rois[roi * 4 + 3]);

    const int x0 = min(max(rx, 0), IMG_W - 1);
    const int y0 = min(max(ry, 0), IMG_H - 1);
    const int w  = min(max(rw, 1), IMG_W - x0);
    const int h  = min(max(rh, 1), IMG_H - y0);

    // TF1 resize (align_corners=False): src = dst * (in/out); exact fp32 div
    const float sx = (float)w / (float)POOL;
    const float sy = (float)h / (float)POOL;

    // ---- horizontal coords: identical for every py in this ROI ----
    int  e0[POOL], e1[POOL];
    float fxv[POOL];
    #pragma unroll
    for (int px = 0; px < POOL; ++px) {
        const float xs = (float)px * sx;
        int ix0 = (int)floorf(xs);
        fxv[px] = xs - (float)ix0;          // frac BEFORE clamp (matches ref)
        ix0 = min(ix0, w - 1);
        const int ix1 = min(ix0 + 1, w - 1);
        e0[px] = (x0 + ix0) * IMG_C;
        e1[px] = (x0 + ix1) * IMG_C;
    }

    for (int j = 0; j < npy; ++j) {
        const int py = pyA + j;
        const float ys = (float)py * sy;
        int iy0 = (int)floorf(ys);
        const float fy = ys - (float)iy0;
        iy0 = min(iy0, h - 1);
        const int iy1 = min(iy0 + 1, h - 1);

        const float* __restrict__ row0 = img + (long)((y0 + iy0) * IMG_W) * IMG_C + c;
        const float* __restrict__ row1 = img + (long)((y0 + iy1) * IMG_W) * IMG_C + c;
        float* __restrict__ obase =
            out + ((long)roi * (POOL * POOL) + py * POOL) * IMG_C + c;

        #pragma unroll
        for (int px = 0; px < POOL; ++px) {
            const float4 v00 = *(const float4*)(row0 + e0[px]);
            const float4 v01 = *(const float4*)(row0 + e1[px]);
            const float4 v10 = *(const float4*)(row1 + e0[px]);
            const float4 v11 = *(const float4*)(row1 + e1[px]);

            const float4 r = bilerp(v00, v01, v10, v11, fxv[px], fy);
            __stcs((float4*)(obase + px * IMG_C), r);   // don't pollute L2/L1
        }
    }
}

extern "C" void kernel_launch(void* const* d_in, const int* in_sizes, int n_in,
                              void* d_out, int out_size)
{
    const float* img  = (const float*)d_in[0];
    const float* rois = (const float*)d_in[1];
    float* out = (float*)d_out;

    const int nblocks = NUM_ROIS * 4;  // 1200
    roi_pool_kernel<<<nblocks, 128>>>(img, rois, out);
}

// round 7
// speedup vs baseline: 1.1569x; 1.1544x over previous
#include <cuda_runtime.h>

#define POOL 7
#define NUM_ROIS 300
#define IMG_H 200
#define IMG_W 200
#define IMG_C 512

// Bilinear with dead-load elimination: when fx==0 the x-interpolation is
// exactly v00 (skip v01/v11 loads); when fy==0 the y-interpolation is exactly
// the top row (skip v10/v11). Predicates are uniform per CTA (depend only on
// roi/px/py), so there is no intra-warp divergence. This cuts ~25% of the L2
// read traffic, which the R1-R6 data shows is the binding resource.
__device__ __forceinline__ void do_px(
    const float* __restrict__ row0, const float* __restrict__ row1,
    float* __restrict__ obase, int px,
    float sx, int w, int x0, bool needY, float fy)
{
    const float xs = (float)px * sx;
    int ix0 = (int)floorf(xs);
    const float fx = xs - (float)ix0;      // frac BEFORE clamp (matches ref)
    ix0 = min(ix0, w - 1);
    const int ix1 = min(ix0 + 1, w - 1);
    const bool needX = (fx != 0.0f) && (ix1 != ix0);

    const int e0 = (x0 + ix0) * IMG_C;
    const int e1 = (x0 + ix1) * IMG_C;
    const float gx = 1.0f - fx;
    const float gy = 1.0f - fy;

    float4 top;
    {
        const float4 v00 = *(const float4*)(row0 + e0);
        if (needX) {
            const float4 v01 = *(const float4*)(row0 + e1);
            top.x = v00.x * gx + v01.x * fx;
            top.y = v00.y * gx + v01.y * fx;
            top.z = v00.z * gx + v01.z * fx;
            top.w = v00.w * gx + v01.w * fx;
        } else {
            top = v00;
        }
    }

    float4 r;
    if (needY) {
        float4 bot;
        const float4 v10 = *(const float4*)(row1 + e0);
        if (needX) {
            const float4 v11 = *(const float4*)(row1 + e1);
            bot.x = v10.x * gx + v11.x * fx;
            bot.y = v10.y * gx + v11.y * fx;
            bot.z = v10.z * gx + v11.z * fx;
            bot.w = v10.w * gx + v11.w * fx;
        } else {
            bot = v10;
        }
        r.x = top.x * gy + bot.x * fy;
        r.y = top.y * gy + bot.y * fy;
        r.z = top.z * gy + bot.z * fy;
        r.w = top.w * gy + bot.w * fy;
    } else {
        r = top;
    }

    __stcs((float4*)(obase + px * IMG_C), r);
}

// One block per (roi, py, px-half): half 0 -> px {0..3}, half 1 -> px {4..6}.
// 128 threads, 4 channels each (float4).
__global__ __launch_bounds__(128) void roi_pool_kernel(
    const float* __restrict__ img,   // [H, W, C]
    const float* __restrict__ rois,  // [NUM_ROIS, 4] (x, y, w, h) as float
    float* __restrict__ out)         // [NUM_ROIS, POOL, POOL, C]
{
    const int b    = blockIdx.x;          // 0..4199
    const int half = b & 1;
    const int rp   = b >> 1;              // roi*7 + py
    const int roi  = rp / POOL;
    const int py   = rp - roi * POOL;
    const int c    = threadIdx.x * 4;

    // ---- ROI geometry (uniform across block) ----
    const int rx = (int)__ldg(&rois[roi * 4 + 0]);
    const int ry = (int)__ldg(&rois[roi * 4 + 1]);
    const int rw = (int)__ldg(&rois[roi * 4 + 2]);
    const int rh = (int)__ldg(&rois[roi * 4 + 3]);

    const int x0 = min(max(rx, 0), IMG_W - 1);
    const int y0 = min(max(ry, 0), IMG_H - 1);
    const int w  = min(max(rw, 1), IMG_W - x0);
    const int h  = min(max(rh, 1), IMG_H - y0);

    // TF1 resize (align_corners=False): src = dst * (in/out); exact fp32 div
    const float sx = (float)w / (float)POOL;
    const float sy = (float)h / (float)POOL;

    // ---- vertical coords (fixed for this block) ----
    const float ys = (float)py * sy;
    int iy0 = (int)floorf(ys);
    const float fy = ys - (float)iy0;
    iy0 = min(iy0, h - 1);
    const int iy1 = min(iy0 + 1, h - 1);
    const bool needY = (fy != 0.0f) && (iy1 != iy0);

    const float* __restrict__ row0 = img + (long)((y0 + iy0) * IMG_W) * IMG_C + c;
    const float* __restrict__ row1 = img + (long)((y0 + iy1) * IMG_W) * IMG_C + c;
    float* __restrict__ obase = out + (long)rp * (POOL * IMG_C) + c;

    if (half == 0) {
        do_px(row0, row1, obase, 0, sx, w, x0, needY, fy);
        do_px(row0, row1, obase, 1, sx, w, x0, needY, fy);
        do_px(row0, row1, obase, 2, sx, w, x0, needY, fy);
        do_px(row0, row1, obase, 3, sx, w, x0, needY, fy);
    } else {
        do_px(row0, row1, obase, 4, sx, w, x0, needY, fy);
        do_px(row0, row1, obase, 5, sx, w, x0, needY, fy);
        do_px(row0, row1, obase, 6, sx, w, x0, needY, fy);
    }
}

extern "C" void kernel_launch(void* const* d_in, const int* in_sizes, int n_in,
                              void* d_out, int out_size)
{
    const float* img  = (const float*)d_in[0];
    const float* rois = (const float*)d_in[1];
    float* out = (float*)d_out;

    const int nblocks = NUM_ROIS * POOL * 2;  // 4200
    roi_pool_kernel<<<nblocks, 128>>>(img, rois, out);
}

// round 8
// speedup vs baseline: 1.1626x; 1.0049x over previous
#include <cuda_runtime.h>

#define POOL 7
#define NUM_ROIS 300
#define IMG_H 200
#define IMG_W 200
#define IMG_C 512

// Lerp helpers
__device__ __forceinline__ float4 lerp4(float4 a, float4 b, float ga, float fb)
{
    float4 r;
    r.x = a.x * ga + b.x * fb;
    r.y = a.y * ga + b.y * fb;
    r.z = a.z * ga + b.z * fb;
    r.w = a.w * ga + b.w * fb;
    return r;
}

struct HCoord { int e0, e1; float fx; bool needX; };

__device__ __forceinline__ HCoord hcoord(int px, float sx, int w, int x0)
{
    HCoord hc;
    const float xs = (float)px * sx;
    int ix0 = (int)floorf(xs);
    hc.fx = xs - (float)ix0;            // frac BEFORE clamp (matches ref)
    ix0 = min(ix0, w - 1);
    const int ix1 = min(ix0 + 1, w - 1);
    hc.needX = (hc.fx != 0.0f) && (ix1 != ix0);
    hc.e0 = (x0 + ix0) * IMG_C;
    hc.e1 = (x0 + ix1) * IMG_C;
    return hc;
}

// Process a pair of px positions with batched loads:
// issue all unconditionally-needed loads first, then the predicated ones,
// THEN compute. Predicates are uniform per CTA (no divergence).
__device__ __forceinline__ void do_px2(
    const float* __restrict__ row0, const float* __restrict__ row1,
    float* __restrict__ obase, int pxa, int pxb,
    float sx, int w, int x0, bool needY, float fy)
{
    const HCoord a = hcoord(pxa, sx, w, x0);
    const HCoord b = hcoord(pxb, sx, w, x0);

    // ---- load phase (max batching) ----
    const float4 A00 = *(const float4*)(row0 + a.e0);
    const float4 B00 = *(const float4*)(row0 + b.e0);

    float4 A10, B10;
    if (needY) {
        A10 = *(const float4*)(row1 + a.e0);
        B10 = *(const float4*)(row1 + b.e0);
    }
    float4 A01, A11;
    if (a.needX) {
        A01 = *(const float4*)(row0 + a.e1);
        if (needY) A11 = *(const float4*)(row1 + a.e1);
    }
    float4 B01, B11;
    if (b.needX) {
        B01 = *(const float4*)(row0 + b.e1);
        if (needY) B11 = *(const float4*)(row1 + b.e1);
    }

    // ---- compute phase ----
    const float gy = 1.0f - fy;

    float4 ra;
    {
        const float ga = 1.0f - a.fx;
        float4 top = a.needX ? lerp4(A00, A01, ga, a.fx) : A00;
        if (needY) {
            float4 bot = a.needX ? lerp4(A10, A11, ga, a.fx) : A10;
            ra = lerp4(top, bot, gy, fy);
        } else {
            ra = top;
        }
    }
    float4 rb;
    {
        const float gb = 1.0f - b.fx;
        float4 top = b.needX ? lerp4(B00, B01, gb, b.fx) : B00;
        if (needY) {
            float4 bot = b.needX ? lerp4(B10, B11, gb, b.fx) : B10;
            rb = lerp4(top, bot, gy, fy);
        } else {
            rb = top;
        }
    }

    __stcs((float4*)(obase + pxa * IMG_C), ra);
    __stcs((float4*)(obase + pxb * IMG_C), rb);
}

__device__ __forceinline__ void do_px1(
    const float* __restrict__ row0, const float* __restrict__ row1,
    float* __restrict__ obase, int px,
    float sx, int w, int x0, bool needY, float fy)
{
    const HCoord a = hcoord(px, sx, w, x0);

    const float4 A00 = *(const float4*)(row0 + a.e0);
    float4 A10;
    if (needY) A10 = *(const float4*)(row1 + a.e0);
    float4 A01, A11;
    if (a.needX) {
        A01 = *(const float4*)(row0 + a.e1);
        if (needY) A11 = *(const float4*)(row1 + a.e1);
    }

    const float gy = 1.0f - fy;
    const float ga = 1.0f - a.fx;
    float4 top = a.needX ? lerp4(A00, A01, ga, a.fx) : A00;
    float4 r;
    if (needY) {
        float4 bot = a.needX ? lerp4(A10, A11, ga, a.fx) : A10;
        r = lerp4(top, bot, gy, fy);
    } else {
        r = top;
    }
    __stcs((float4*)(obase + px * IMG_C), r);
}

// One block per (roi, py, px-half): half 0 -> px {0..3}, half 1 -> px {4..6}.
// 128 threads, 4 channels each (float4).
__global__ __launch_bounds__(128) void roi_pool_kernel(
    const float* __restrict__ img,   // [H, W, C]
    const float* __restrict__ rois,  // [NUM_ROIS, 4] (x, y, w, h) as float
    float* __restrict__ out)         // [NUM_ROIS, POOL, POOL, C]
{
    const int b    = blockIdx.x;          // 0..4199
    const int half = b & 1;
    const int rp   = b >> 1;              // roi*7 + py
    const int roi  = rp / POOL;
    const int py   = rp - roi * POOL;
    const int c    = threadIdx.x * 4;

    // ---- ROI geometry (uniform across block) ----
    const int rx = (int)__ldg(&rois[roi * 4 + 0]);
    const int ry = (int)__ldg(&rois[roi * 4 + 1]);
    const int rw = (int)__ldg(&rois[roi * 4 + 2]);
    const int rh = (int)__ldg(&rois[roi * 4 + 3]);

    const int x0 = min(max(rx, 0), IMG_W - 1);
    const int y0 = min(max(ry, 0), IMG_H - 1);
    const int w  = min(max(rw, 1), IMG_W - x0);
    const int h  = min(max(rh, 1), IMG_H - y0);

    // TF1 resize (align_corners=False): src = dst * (in/out); exact fp32 div
    const float sx = (float)w / (float)POOL;
    const float sy = (float)h / (float)POOL;

    // ---- vertical coords (fixed for this block) ----
    const float ys = (float)py * sy;
    int iy0 = (int)floorf(ys);
    const float fy = ys - (float)iy0;
    iy0 = min(iy0, h - 1);
    const int iy1 = min(iy0 + 1, h - 1);
    const bool needY = (fy != 0.0f) && (iy1 != iy0);

    const float* __restrict__ row0 = img + (long)((y0 + iy0) * IMG_W) * IMG_C + c;
    const float* __restrict__ row1 = img + (long)((y0 + iy1) * IMG_W) * IMG_C + c;
    float* __restrict__ obase = out + (long)rp * (POOL * IMG_C) + c;

    if (half == 0) {
        do_px2(row0, row1, obase, 0, 1, sx, w, x0, needY, fy);
        do_px2(row0, row1, obase, 2, 3, sx, w, x0, needY, fy);
    } else {
        do_px2(row0, row1, obase, 4, 5, sx, w, x0, needY, fy);
        do_px1(row0, row1, obase, 6,    sx, w, x0, needY, fy);
    }
}

extern "C" void kernel_launch(void* const* d_in, const int* in_sizes, int n_in,
                              void* d_out, int out_size)
{
    const float* img  = (const float*)d_in[0];
    const float* rois = (const float*)d_in[1];
    float* out = (float*)d_out;

    const int nblocks = NUM_ROIS * POOL * 2;  // 4200
    roi_pool_kernel<<<nblocks, 128>>>(img, rois, out);
}

// round 9
// speedup vs baseline: 1.1830x; 1.0175x over previous
#include <cuda_runtime.h>

#define POOL 7
#define NUM_ROIS 300
#define IMG_H 200
#define IMG_W 200
#define IMG_C 512

#define CP16(dst_u32, src) \
    asm volatile("cp.async.cg.shared.global [%0], [%1], 16;" :: "r"(dst_u32), "l"(src))
#define CP_COMMIT() asm volatile("cp.async.commit_group;")
#define CP_WAIT(N)  asm volatile("cp.async.wait_group %0;" :: "n"(N))

__device__ __forceinline__ unsigned su32(const void* p) {
    return (unsigned)__cvta_generic_to_shared(p);
}

__device__ __forceinline__ float4 lerp4(float4 a, float4 b, float ga, float fb)
{
    float4 r;
    r.x = a.x * ga + b.x * fb;
    r.y = a.y * ga + b.y * fb;
    r.z = a.z * ga + b.z * fb;
    r.w = a.w * ga + b.w * fb;
    return r;
}

struct HCoord { int e0, e1; float fx; bool needX; };

__device__ __forceinline__ HCoord hcoord(int px, float sx, int w, int x0)
{
    HCoord hc;
    const float xs = (float)px * sx;
    int ix0 = (int)floorf(xs);
    hc.fx = xs - (float)ix0;            // frac BEFORE clamp (matches ref)
    ix0 = min(ix0, w - 1);
    const int ix1 = min(ix0 + 1, w - 1);
    hc.needX = (hc.fx != 0.0f) && (ix1 != ix0);
    hc.e0 = (x0 + ix0) * IMG_C;
    hc.e1 = (x0 + ix1) * IMG_C;
    return hc;
}

// Issue cp.asyncs for one px into its [4][128] corner buffer (skip dead loads).
__device__ __forceinline__ void prefetch_px(
    float4 (&pb)[4][128], const float* __restrict__ row0,
    const float* __restrict__ row1, bool needY, const HCoord& hc, int t)
{
    CP16(su32(&pb[0][t]), row0 + hc.e0);
    if (hc.needX) CP16(su32(&pb[1][t]), row0 + hc.e1);
    if (needY) {
        CP16(su32(&pb[2][t]), row1 + hc.e0);
        if (hc.needX) CP16(su32(&pb[3][t]), row1 + hc.e1);
    }
}

// Consume one px's buffered corners, interpolate, store.
__device__ __forceinline__ void compute_px(
    const float4 (&pb)[4][128], float* __restrict__ obase, int px,
    bool needY, float fy, const HCoord& hc, int t)
{
    const float gx = 1.0f - hc.fx;
    const float gy = 1.0f - fy;

    const float4 v00 = pb[0][t];
    float4 top = hc.needX ? lerp4(v00, pb[1][t], gx, hc.fx) : v00;
    float4 r;
    if (needY) {
        const float4 v10 = pb[2][t];
        const float4 bot = hc.needX ? lerp4(v10, pb[3][t], gx, hc.fx) : v10;
        r = lerp4(top, bot, gy, fy);
    } else {
        r = top;
    }
    __stcs((float4*)(obase + px * IMG_C), r);
}

// One block per (roi, py, px-half): half 0 -> px {0..3}, half 1 -> px {4..6}.
// 128 threads, 4 channels each. All GMEM reads go through cp.async into SMEM
// (register-free MLP: every needed load for the whole CTA is in flight before
// any compute). Thread-private buffers -> no __syncthreads needed.
__global__ __launch_bounds__(128) void roi_pool_kernel(
    const float* __restrict__ img,   // [H, W, C]
    const float* __restrict__ rois,  // [NUM_ROIS, 4] (x, y, w, h) as float
    float* __restrict__ out)         // [NUM_ROIS, POOL, POOL, C]
{
    __shared__ float4 buf[2][2][4][128];   // [stage][pxInPair][corner][tid] = 32 KB

    const int b    = blockIdx.x;           // 0..4199
    const int half = b & 1;
    const int rp   = b >> 1;               // roi*7 + py
    const int roi  = rp / POOL;
    const int py   = rp - roi * POOL;
    const int t    = threadIdx.x;
    const int c    = t * 4;

    // ---- ROI geometry (uniform across block) ----
    const int rx = (int)__ldg(&rois[roi * 4 + 0]);
    const int ry = (int)__ldg(&rois[roi * 4 + 1]);
    const int rw = (int)__ldg(&rois[roi * 4 + 2]);
    const int rh = (int)__ldg(&rois[roi * 4 + 3]);

    const int x0 = min(max(rx, 0), IMG_W - 1);
    const int y0 = min(max(ry, 0), IMG_H - 1);
    const int w  = min(max(rw, 1), IMG_W - x0);
    const int h  = min(max(rh, 1), IMG_H - y0);

    // TF1 resize (align_corners=False): src = dst * (in/out); exact fp32 div
    const float sx = (float)w / (float)POOL;
    const float sy = (float)h / (float)POOL;

    // ---- vertical coords (fixed for this block) ----
    const float ys = (float)py * sy;
    int iy0 = (int)floorf(ys);
    const float fy = ys - (float)iy0;      // frac BEFORE clamp
    iy0 = min(iy0, h - 1);
    const int iy1 = min(iy0 + 1, h - 1);
    const bool needY = (fy != 0.0f) && (iy1 != iy0);

    const float* __restrict__ row0 = img + (long)((y0 + iy0) * IMG_W) * IMG_C + c;
    const float* __restrict__ row1 = img + (long)((y0 + iy1) * IMG_W) * IMG_C + c;
    float* __restrict__ obase = out + (long)rp * (POOL * IMG_C) + c;

    const int px0 = half ? 4 : 0;
    const bool has4th = (half == 0);       // half 1 covers only 3 px

    const HCoord h0 = hcoord(px0,     sx, w, x0);
    const HCoord h1 = hcoord(px0 + 1, sx, w, x0);
    const HCoord h2 = hcoord(px0 + 2, sx, w, x0);
    HCoord h3;
    if (has4th) h3 = hcoord(px0 + 3, sx, w, x0);

    // ---- issue ALL loads up front (2 commit groups) ----
    prefetch_px(buf[0][0], row0, row1, needY, h0, t);
    prefetch_px(buf[0][1], row0, row1, needY, h1, t);
    CP_COMMIT();
    prefetch_px(buf[1][0], row0, row1, needY, h2, t);
    if (has4th) prefetch_px(buf[1][1], row0, row1, needY, h3, t);
    CP_COMMIT();

    // ---- drain + compute ----
    CP_WAIT(1);
    compute_px(buf[0][0], obase, px0,     needY, fy, h0, t);
    compute_px(buf[0][1], obase, px0 + 1, needY, fy, h1, t);

    CP_WAIT(0);
    compute_px(buf[1][0], obase, px0 + 2, needY, fy, h2, t);
    if (has4th) compute_px(buf[1][1], obase, px0 + 3, needY, fy, h3, t);
}

extern "C" void kernel_launch(void* const* d_in, const int* in_sizes, int n_in,
                              void* d_out, int out_size)
{
    const float* img  = (const float*)d_in[0];
    const float* rois = (const float*)d_in[1];
    float* out = (float*)d_out;

    const int nblocks = NUM_ROIS * POOL * 2;  // 4200
    roi_pool_kernel<<<nblocks, 128>>>(img, rois, out);
}